// round 9
// baseline (speedup 1.0000x reference)
#include <cuda_runtime.h>
#include <stdint.h>

// Problem constants (fixed by the reference).
#define NPRE     6000
#define NPOST    2000
#define NB       94          // ceil(NPRE/64)
#define NROWS    (NB * 64)   // 6016, padded
#define HB       32768       // score histogram buckets (scores in [0,1))
#define CAND_MAX 8192
#define BCAP     256         // per-bucket sort capacity
#define SCUT     (HB - 256)  // stash cut bucket
#define STASH_CAP 32768
#define SLOCAL   256         // per-block stash buffer

// ---------------- persistent device scratch (static zero-init at load) ------
__device__ unsigned           g_hist[HB];
__device__ unsigned           g_cnt[HB];
__device__ unsigned           g_base[HB];   // descending exclusive rank base
__device__ int                g_thresh;
__device__ int                g_ready;      // thresh-done flag (fused kernel)
__device__ int                g_nstash;
__device__ unsigned long long g_stash[STASH_CAP];
__device__ unsigned long long g_cand[CAND_MAX];
// SoA boxes (padded rows >= NPRE are never written -> stay zero)
__device__ float              g_y1[NROWS], g_x1[NROWS], g_y2[NROWS], g_x2[NROWS];
__device__ float              g_pa[NROWS];      // 0.7f * area
__device__ float              g_scores[NROWS];
// transposed mask: g_maskT[col_group][row]
__device__ unsigned long long g_maskT[NB][NROWS];
__device__ unsigned long long g_alive[NB];
__device__ int                g_kept[NPOST];
__device__ int                g_kcount;
__device__ int                g_done;

__device__ __forceinline__ int score_bucket(float s) {
    int b = (int)(s * 32768.0f);
    return max(0, min(HB - 1, b));
}

// ---------------- K1: histogram + block-aggregated stash --------------------
__global__ void hist_stash_k(const float4* __restrict__ s4, int n4) {
    __shared__ unsigned long long s_stash[SLOCAL];
    __shared__ int s_scnt, s_sbase;
    if (threadIdx.x == 0) s_scnt = 0;
    __syncthreads();
    int i = blockIdx.x * blockDim.x + threadIdx.x;
    int stride = gridDim.x * blockDim.x;
    for (; i < n4; i += stride) {
        float4 v = s4[i];
        float e[4] = {v.x, v.y, v.z, v.w};
#pragma unroll
        for (int c = 0; c < 4; c++) {
            int b = score_bucket(e[c]);
            atomicAdd(&g_hist[b], 1u);
            if (b >= SCUT) {
                unsigned idx = (unsigned)(4 * i + c);
                unsigned long long key =
                    ((unsigned long long)__float_as_uint(e[c]) << 32)
                  | (unsigned long long)(0xFFFFFFFFu - idx);
                int p = atomicAdd(&s_scnt, 1);
                if (p < SLOCAL) s_stash[p] = key;
                else {                        // rare overflow: direct global
                    int q = atomicAdd(&g_nstash, 1);
                    if (q < STASH_CAP) g_stash[q] = key;
                }
            }
        }
    }
    __syncthreads();
    int cnt = s_scnt; if (cnt > SLOCAL) cnt = SLOCAL;
    if (threadIdx.x == 0) s_sbase = (cnt > 0) ? atomicAdd(&g_nstash, cnt) : 0;
    __syncthreads();
    for (int k = threadIdx.x; k < cnt; k += blockDim.x) {
        int q = s_sbase + k;
        if (q < STASH_CAP) g_stash[q] = s_stash[k];
    }
}

// ---------------- K2: FUSED threshold (block 0) + counting-sort scatter -----
// All 512 blocks are co-resident (256 thr, low regs), so the flag wait is safe.
__global__ void threshcompact_k(const float4* __restrict__ s4, int n4) {
    __shared__ unsigned s_scan[256];
    int t = threadIdx.x;

    if (blockIdx.x == 0) {
        // --- threshold + per-bucket descending rank bases (256 threads) ---
        int lo = HB - (t + 1) * 128;   // thread owns buckets [lo, lo+128); t=0 top
        unsigned sum = 0;
        const uint4* h4 = (const uint4*)g_hist;
#pragma unroll
        for (int k = 0; k < 32; k++) {
            uint4 u = h4[(lo >> 2) + k];
            sum += u.x + u.y + u.z + u.w;
        }
        s_scan[t] = sum;
        __syncthreads();
        for (int off = 1; off < 256; off <<= 1) {
            unsigned v = (t >= off) ? s_scan[t - off] : 0u;
            __syncthreads();
            s_scan[t] += v;
            __syncthreads();
        }
        unsigned run = s_scan[t] - sum;   // count strictly above this chunk
        for (int b = 127; b >= 0; --b) {
            unsigned c = g_hist[lo + b];
            g_base[lo + b] = run;
            if (run < (unsigned)NPRE && run + c >= (unsigned)NPRE) g_thresh = lo + b;
            run += c;
        }
        if (t == 255 && s_scan[255] < (unsigned)NPRE) g_thresh = 0;  // degenerate
        __syncthreads();
        if (t == 0) { __threadfence(); atomicExch(&g_ready, 1); }
        __syncthreads();
    } else {
        if (t == 0) {
            while (atomicAdd(&g_ready, 0) == 0) { }
            __threadfence();
        }
        __syncthreads();
    }

    // --- scatter (stash fast path / full fallback) ---
    int T = g_thresh;
    int ns = g_nstash;
    int tid = blockIdx.x * blockDim.x + t;
    int stride = gridDim.x * blockDim.x;
    if (T >= SCUT && ns <= STASH_CAP) {
        for (int i = tid; i < ns; i += stride) {
            unsigned long long key = g_stash[i];
            int b = score_bucket(__uint_as_float((unsigned)(key >> 32)));
            if (b >= T) {
                unsigned pos = g_base[b] + atomicAdd(&g_cnt[b], 1u);
                if (pos < CAND_MAX) g_cand[pos] = key;
            }
        }
    } else {
        for (int i = tid; i < n4; i += stride) {
            float4 v = s4[i];
            float e[4] = {v.x, v.y, v.z, v.w};
#pragma unroll
            for (int c = 0; c < 4; c++) {
                int b = score_bucket(e[c]);
                if (b >= T) {
                    unsigned pos = g_base[b] + atomicAdd(&g_cnt[b], 1u);
                    if (pos < CAND_MAX) {
                        unsigned idx = (unsigned)(4 * i + c);
                        g_cand[pos] = ((unsigned long long)__float_as_uint(e[c]) << 32)
                                    | (unsigned long long)(0xFFFFFFFFu - idx);
                    }
                }
            }
        }
    }
}

// ---------------- K3: per-bucket bitonic sort FUSED with decode -------------
__global__ void bsort_decode_k(const float* __restrict__ enc,
                               const float* __restrict__ anch, int n) {
    __shared__ unsigned long long s[BCAP];
    int T = g_thresh;
    int t = threadIdx.x;                           // 128 threads
    for (int b = T + blockIdx.x; b < HB; b += gridDim.x) {
        unsigned base = g_base[b];
        if (base >= (unsigned)NPRE) continue;      // ranks never read
        unsigned cnt = g_cnt[b];
        if (cnt == 0) continue;
        int m = (cnt < (unsigned)BCAP) ? (int)cnt : BCAP;
        if (m > 1) {
            int kmax = 2; while (kmax < m) kmax <<= 1;
            for (int i = t; i < kmax; i += 128) s[i] = (i < m) ? g_cand[base + i] : 0ull;
            __syncthreads();
            for (int k = 2; k <= kmax; k <<= 1) {
                for (int j = k >> 1; j > 0; j >>= 1) {
                    for (int p = t; p < (kmax >> 1); p += 128) {
                        int i = ((p & ~(j - 1)) << 1) | (p & (j - 1));
                        int x = i | j;
                        unsigned long long a = s[i], bb = s[x];
                        bool desc = ((i & k) == 0);
                        if (desc ? (a < bb) : (a > bb)) { s[i] = bb; s[x] = a; }
                    }
                    __syncthreads();
                }
            }
        }
        // decode ranks [base, base+cnt) ∩ [0, NPRE) straight from shared
        int lim = (int)cnt;
        if (base + lim > (unsigned)NPRE) lim = NPRE - (int)base;
        if (base + lim > (unsigned)CAND_MAX) lim = CAND_MAX - (int)base;
        for (int i = t; i < lim; i += 128) {
            unsigned long long key = (m > 1 && i < m) ? s[i] : g_cand[base + i];
            int r = (int)base + i;
            float y1 = 0.f, x1 = 0.f, y2 = 0.f, x2 = 0.f, sc = 0.f;
            unsigned idx = 0xFFFFFFFFu - (unsigned)(key & 0xFFFFFFFFull);
            if (idx < (unsigned)n) {
                sc = __uint_as_float((unsigned)(key >> 32));
                float4 a = ((const float4*)anch)[idx];   // [y1, x1, y2, x2]
                float4 e = ((const float4*)enc)[idx];    // [ty, tx, th, tw]
                float ha = a.z - a.x, wa = a.w - a.y;
                float cya = a.x + 0.5f * ha, cxa = a.y + 0.5f * wa;
                float cy = e.x * ha + cya;
                float cx = e.y * wa + cxa;
                float h  = expf(e.z) * ha;
                float w  = expf(e.w) * wa;
                y1 = cy - 0.5f * h; x1 = cx - 0.5f * w;
                y2 = cy + 0.5f * h; x2 = cx + 0.5f * w;
            }
            g_y1[r] = y1; g_x1[r] = x1; g_y2[r] = y2; g_x2[r] = x2;
            g_pa[r] = 0.7f * (y2 - y1) * (x2 - x1);
            g_scores[r] = sc;
        }
        __syncthreads();
    }
}

// ---------------- K4: IoU bitmask, transposed coalesced writes --------------
// iou > 0.7  <=>  1.7*inter > 0.7*areaA + 0.7*areaB
__global__ void mask_k(int col0) {
    if (*(volatile int*)&g_done) return;
    int bx = col0 + blockIdx.x;
    int by = blockIdx.y;
    if (bx >= NB || by > bx) return;

    __shared__ float4 colb[64];
    __shared__ float  colp[64];
    int t = threadIdx.x;
    int j = bx * 64 + t;
    colb[t] = make_float4(g_y1[j], g_x1[j], g_y2[j], g_x2[j]);
    colp[t] = g_pa[j];
    __syncthreads();

    int i = by * 64 + t;
    float y1 = g_y1[i], x1 = g_x1[i], y2 = g_y2[i], x2 = g_x2[i];
    float pa = g_pa[i];
    unsigned long long m = 0ull;

    if (bx > by) {
#pragma unroll 16
        for (int c = 0; c < 64; c++) {
            float4 cb = colb[c];
            float iy1 = fmaxf(y1, cb.x), ix1 = fmaxf(x1, cb.y);
            float iy2 = fminf(y2, cb.z), ix2 = fminf(x2, cb.w);
            float dy = fmaxf(iy2 - iy1, 0.f), dx = fmaxf(ix2 - ix1, 0.f);
            bool cond = fmaf(1.7f, dy * dx, -pa) > colp[c];
            m |= ((unsigned long long)cond) << c;
        }
    } else {  // diagonal block: only c > t
        for (int c = t + 1; c < 64; c++) {
            float4 cb = colb[c];
            float iy1 = fmaxf(y1, cb.x), ix1 = fmaxf(x1, cb.y);
            float iy2 = fminf(y2, cb.z), ix2 = fminf(x2, cb.w);
            float dy = fmaxf(iy2 - iy1, 0.f), dx = fmaxf(ix2 - ix1, 0.f);
            bool cond = fmaf(1.7f, dy * dx, -pa) > colp[c];
            m |= ((unsigned long long)cond) << c;
        }
    }
    g_maskT[bx][i] = m;   // coalesced across t
}

// ---------------- K5: NMS partial reduce (role-split pipelined) -------------
__global__ void nms_part_k(int g0, int g1) {
    if (*(volatile int*)&g_done) return;
    __shared__ int                s_kept[NPOST];
    __shared__ unsigned long long s_alive[NB];
    __shared__ unsigned long long s_col[64];
    __shared__ unsigned long long s_gnext[64];
    __shared__ unsigned long long s_crossbuf[2];
    __shared__ unsigned long long s_colOR;
    __shared__ unsigned long long s_alivew;
    __shared__ int s_kc;
    int t = threadIdx.x;                       // 256 threads
    int kcount = g_kcount;
    for (int i = t; i < kcount; i += 256) s_kept[i] = g_kept[i];
    for (int i = t; i < NB; i += 256) s_alive[i] = g_alive[i];
    if (t == 0) { s_crossbuf[0] = 0ull; s_crossbuf[1] = 0ull; s_colOR = 0ull; }
    __syncthreads();
    // prologue: cross for g0 over rows < g0*64 (alive only)
    {
        unsigned long long p = 0ull;
        for (int r = t; r < g0 * 64; r += 256)
            if ((s_alive[r >> 6] >> (r & 63)) & 1ull) p |= g_maskT[g0][r];
        if (p) atomicOr(&s_crossbuf[g0 & 1], p);
    }
    __syncthreads();

    if (g1 > NB) g1 = NB;
    for (int g = g0; g < g1; ++g) {
        int base = g * 64;
        int n = NPRE - base; if (n > 64) n = 64;
        int cur = g & 1, nxt = cur ^ 1;
        bool haveNext = (g + 1 < NB);
        // ---- Phase A (role split): current cols | next-col prefetch | next cross
        if (t < 64) {
            unsigned long long w = g_maskT[g][base + t];
            s_col[t] = w;
            if (w) atomicOr(&s_colOR, w);
        } else if (t < 128) {
            s_gnext[t - 64] = haveNext ? g_maskT[g + 1][base + (t - 64)] : 0ull;
        } else if (haveNext) {
            unsigned long long p = 0ull;
            for (int r = t - 128; r < base; r += 128)
                if ((s_alive[r >> 6] >> (r & 63)) & 1ull) p |= g_maskT[g + 1][r];
            if (p) atomicOr(&s_crossbuf[nxt], p);
        }
        __syncthreads();
        // ---- Phase B: decision
        unsigned long long cross = s_crossbuf[cur];
        unsigned long long colOR = s_colOR;
        unsigned long long rowmask = (n == 64) ? ~0ull : ((1ull << n) - 1ull);
        bool fast = (cross == 0ull && colOR == 0ull && kcount + n <= NPOST);
        if (fast) {
            if (t < n) s_kept[kcount + t] = base + t;
            if (t == 0) { s_kc = kcount + n; s_alivew = rowmask; }
        } else if (t == 0) {
            unsigned long long avail = (~cross) & rowmask;
            unsigned long long alivew = 0ull;
            int kc = kcount;
            while (avail && kc < NPOST) {
                int k1 = __ffsll((long long)avail) - 1;
                unsigned long long r = avail & (avail - 1);
                unsigned long long c1 = s_col[k1];
                int k2 = -1, k3 = -1, k4 = -1;
                unsigned long long c2 = 0, c3 = 0, c4 = 0;
                if (r) { k2 = __ffsll((long long)r) - 1; c2 = s_col[k2]; r &= r - 1;
                    if (r) { k3 = __ffsll((long long)r) - 1; c3 = s_col[k3]; r &= r - 1;
                        if (r) { k4 = __ffsll((long long)r) - 1; c4 = s_col[k4]; r &= r - 1; } } }
                unsigned long long m = c1;
                s_kept[kc++] = base + k1; alivew |= 1ull << k1;
                if (k2 >= 0 && kc < NPOST && !((m >> k2) & 1ull)) { s_kept[kc++] = base + k2; alivew |= 1ull << k2; m |= c2; }
                if (k3 >= 0 && kc < NPOST && !((m >> k3) & 1ull)) { s_kept[kc++] = base + k3; alivew |= 1ull << k3; m |= c3; }
                if (k4 >= 0 && kc < NPOST && !((m >> k4) & 1ull)) { s_kept[kc++] = base + k4; alivew |= 1ull << k4; m |= c4; }
                avail = r & ~m;
            }
            s_kc = kc; s_alivew = alivew;
        }
        __syncthreads();
        // ---- Phase C: combine + bookkeeping
        kcount = s_kc;
        unsigned long long aw = s_alivew;
        if (t < 64 && ((aw >> t) & 1ull)) {
            unsigned long long w = s_gnext[t];
            if (w) atomicOr(&s_crossbuf[nxt], w);
        }
        if (t == 0) { s_alive[g] = aw; s_crossbuf[cur] = 0ull; s_colOR = 0ull; }
        __syncthreads();
        if (kcount >= NPOST) break;
    }
    // epilogue
    int kc0 = g_kcount;
    for (int i = kc0 + t; i < kcount; i += 256) g_kept[i] = s_kept[i];
    for (int i = t; i < NB; i += 256) g_alive[i] = s_alive[i];
    if (t == 0) {
        g_kcount = kcount;
        if (kcount >= NPOST || g1 >= NB) g_done = 1;
    }
}

// ---------------- K6: write output + reset state for next replay ------------
__global__ void finish_k(float* __restrict__ out) {
    int gid = blockIdx.x * blockDim.x + threadIdx.x;
    int gs  = gridDim.x * blockDim.x;
    int kcount = g_kcount;
    // output
    for (int o = gid; o < NPOST; o += gs) {
        if (o < kcount) {
            int i = g_kept[o];
            ((float4*)out)[o] = make_float4(g_y1[i], g_x1[i], g_y2[i], g_x2[i]);
            out[NPOST * 4 + o] = g_scores[i];
        } else {
            ((float4*)out)[o] = make_float4(0.f, 0.f, 0.f, 0.f);
            out[NPOST * 4 + o] = 0.f;
        }
    }
    // reset for next replay (graph edge serializes this after all reads above)
    for (int i = gid; i < HB; i += gs) { g_hist[i] = 0u; g_cnt[i] = 0u; }
    for (int i = gid; i < NB; i += gs) g_alive[i] = 0ull;
    if (gid == 0) {
        g_kcount = 0; g_done = 0; g_nstash = 0; g_ready = 0;
    }
}

// ---------------- launch ----------------------------------------------------
extern "C" void kernel_launch(void* const* d_in, const int* in_sizes, int n_in,
                              void* d_out, int out_size) {
    const float* enc    = (const float*)d_in[0];  // encoded_bboxes [N,4]
    const float* anch   = (const float*)d_in[1];  // anchors        [N,4]
    const float* scores = (const float*)d_in[2];  // scores         [N]
    float* out = (float*)d_out;                   // 2000*4 boxes + 2000 scores
    int n = in_sizes[2];
    int n4 = n / 4;

    hist_stash_k<<<1024, 256>>>((const float4*)scores, n4);
    threshcompact_k<<<512, 256>>>((const float4*)scores, n4);
    bsort_decode_k<<<148, 128>>>(enc, anch, n);

    // two-chunk mask+NMS with early-exit flag; expected exit <= group 40
    mask_k<<<dim3(40, 40), 64>>>(0);
    nms_part_k<<<1, 256>>>(0, 40);
    mask_k<<<dim3(54, 94), 64>>>(40);
    nms_part_k<<<1, 256>>>(40, 94);

    finish_k<<<128, 256>>>(out);
}

// round 10
// speedup vs baseline: 1.4200x; 1.4200x over previous
#include <cuda_runtime.h>
#include <stdint.h>

// Problem constants (fixed by the reference).
#define NPRE     6000
#define NPOST    2000
#define NB       94          // ceil(NPRE/64)
#define NROWS    (NB * 64)   // 6016, padded
#define HB       32768       // score histogram buckets (scores in [0,1))
#define CAND_MAX 8192
#define BCAP     256         // per-bucket sort capacity
#define SCUT     (HB - 256)  // stash cut bucket
#define STASH_CAP 32768
#define SLOCAL   256         // per-block stash buffer

// ---------------- persistent device scratch (static zero-init at load) ------
__device__ unsigned           g_hist[HB];   // used only by the fallback path
__device__ unsigned           g_cnt[HB];
__device__ unsigned           g_base[HB];   // descending exclusive rank base
__device__ int                g_thresh;
__device__ int                g_nstash;
__device__ unsigned long long g_stash[STASH_CAP];
__device__ unsigned long long g_cand[CAND_MAX];
// SoA boxes (padded rows >= NPRE are never written -> stay zero)
__device__ float              g_y1[NROWS], g_x1[NROWS], g_y2[NROWS], g_x2[NROWS];
__device__ float              g_pa[NROWS];      // 0.7f * area
__device__ float              g_scores[NROWS];
// transposed mask: g_maskT[col_group][row]
__device__ unsigned long long g_maskT[NB][NROWS];
__device__ unsigned long long g_alive[NB];
__device__ int                g_kept[NPOST];
__device__ int                g_kcount;
__device__ int                g_done;

__device__ __forceinline__ int score_bucket(float s) {
    int b = (int)(s * 32768.0f);
    return max(0, min(HB - 1, b));
}

// ---------------- K1: pure scan + block-aggregated stash (NO histogram) -----
__global__ void scan_stash_k(const float4* __restrict__ s4, int n4) {
    __shared__ unsigned long long s_stash[SLOCAL];
    __shared__ int s_scnt, s_sbase;
    if (threadIdx.x == 0) s_scnt = 0;
    __syncthreads();
    int i = blockIdx.x * blockDim.x + threadIdx.x;
    int stride = gridDim.x * blockDim.x;
    for (; i < n4; i += stride) {
        float4 v = s4[i];
        float e[4] = {v.x, v.y, v.z, v.w};
#pragma unroll
        for (int c = 0; c < 4; c++) {
            if (score_bucket(e[c]) >= SCUT) {
                unsigned idx = (unsigned)(4 * i + c);
                unsigned long long key =
                    ((unsigned long long)__float_as_uint(e[c]) << 32)
                  | (unsigned long long)(0xFFFFFFFFu - idx);
                int p = atomicAdd(&s_scnt, 1);
                if (p < SLOCAL) s_stash[p] = key;
                else {                        // rare overflow: direct global
                    int q = atomicAdd(&g_nstash, 1);
                    if (q < STASH_CAP) g_stash[q] = key;
                }
            }
        }
    }
    __syncthreads();
    int cnt = s_scnt; if (cnt > SLOCAL) cnt = SLOCAL;
    if (threadIdx.x == 0) s_sbase = (cnt > 0) ? atomicAdd(&g_nstash, cnt) : 0;
    __syncthreads();
    for (int k = threadIdx.x; k < cnt; k += blockDim.x) {
        int q = s_sbase + k;
        if (q < STASH_CAP) g_stash[q] = s_stash[k];
    }
}

// ---------------- K2: threshold + rank bases from the STASH -----------------
// Normal path: histogram the ~15K stash keys into 256 shared buckets.
// Fallback (never taken for this data, kept for exactness): single-block full
// histogram + full scan.
__global__ void thresh_k(const float4* __restrict__ s4, int n4) {
    __shared__ unsigned sh[256];     // counts of buckets [SCUT, HB)
    __shared__ unsigned sc[256];     // suffix-sum workspace (from top)
    __shared__ unsigned sbig[1024];  // fallback scan workspace
    int t = threadIdx.x;             // 1024 threads
    int ns = g_nstash;
    for (int i = t; i < 256; i += 1024) sh[i] = 0;
    __syncthreads();
    int nsc = (ns < STASH_CAP) ? ns : STASH_CAP;
    for (int i = t; i < nsc; i += 1024) {
        unsigned long long key = g_stash[i];
        int b = score_bucket(__uint_as_float((unsigned)(key >> 32)));
        if (b >= SCUT) atomicAdd(&sh[b - SCUT], 1u);
    }
    __syncthreads();
    if (t < 256) sc[t] = sh[255 - t];   // sc[k] = count of bucket HB-1-k
    __syncthreads();
    for (int off = 1; off < 256; off <<= 1) {   // inclusive scan from top
        unsigned v = 0;
        if (t < 256 && t >= off) v = sc[t - off];
        __syncthreads();
        if (t < 256) sc[t] += v;
        __syncthreads();
    }
    unsigned total = sc[255];   // all elements with bucket >= SCUT
    bool ok = (ns <= STASH_CAP) && (total >= (unsigned)NPRE);
    if (ok) {
        if (t < 256) {
            int b = HB - 1 - t;
            unsigned incl = sc[t];
            unsigned above = incl - sh[255 - t];
            g_base[b] = above;
            if (above < (unsigned)NPRE && incl >= (unsigned)NPRE) g_thresh = b;
        }
    } else {
        // ---- exact fallback: full histogram + full descending scan ----
        for (int i = t; i < n4; i += 1024) {
            float4 v = s4[i];
            atomicAdd(&g_hist[score_bucket(v.x)], 1u);
            atomicAdd(&g_hist[score_bucket(v.y)], 1u);
            atomicAdd(&g_hist[score_bucket(v.z)], 1u);
            atomicAdd(&g_hist[score_bucket(v.w)], 1u);
        }
        __syncthreads();
        int lo = HB - (t + 1) * 32;
        unsigned cnts[32];
        unsigned sum = 0;
#pragma unroll
        for (int b = 0; b < 32; b++) { cnts[b] = g_hist[lo + b]; sum += cnts[b]; }
        sbig[t] = sum;
        __syncthreads();
        for (int off = 1; off < 1024; off <<= 1) {
            unsigned v = (t >= off) ? sbig[t - off] : 0u;
            __syncthreads();
            sbig[t] += v;
            __syncthreads();
        }
        unsigned run = sbig[t] - sum;
        for (int b = 31; b >= 0; --b) {
            g_base[lo + b] = run;
            unsigned c = cnts[b];
            if (run < (unsigned)NPRE && run + c >= (unsigned)NPRE) g_thresh = lo + b;
            run += c;
        }
        if (t == 1023 && sbig[1023] < (unsigned)NPRE) g_thresh = 0;
    }
}

// ---------------- K3: counting-sort scatter (stash fast path / fallback) ----
__global__ void compact_k(const float4* __restrict__ s4, int n4) {
    int T = g_thresh;
    int ns = g_nstash;
    bool valid = (T >= SCUT) && (ns <= STASH_CAP);
    int tid = blockIdx.x * blockDim.x + threadIdx.x;
    int stride = gridDim.x * blockDim.x;
    if (valid) {
        for (int i = tid; i < ns; i += stride) {
            unsigned long long key = g_stash[i];
            int b = score_bucket(__uint_as_float((unsigned)(key >> 32)));
            if (b >= T) {
                unsigned pos = g_base[b] + atomicAdd(&g_cnt[b], 1u);
                if (pos < CAND_MAX) g_cand[pos] = key;
            }
        }
    } else {
        for (int i = tid; i < n4; i += stride) {
            float4 v = s4[i];
            float e[4] = {v.x, v.y, v.z, v.w};
#pragma unroll
            for (int c = 0; c < 4; c++) {
                int b = score_bucket(e[c]);
                if (b >= T) {
                    unsigned pos = g_base[b] + atomicAdd(&g_cnt[b], 1u);
                    if (pos < CAND_MAX) {
                        unsigned idx = (unsigned)(4 * i + c);
                        g_cand[pos] = ((unsigned long long)__float_as_uint(e[c]) << 32)
                                    | (unsigned long long)(0xFFFFFFFFu - idx);
                    }
                }
            }
        }
    }
}

// ---------------- K4: per-bucket bitonic sort FUSED with decode -------------
__global__ void bsort_decode_k(const float* __restrict__ enc,
                               const float* __restrict__ anch, int n) {
    __shared__ unsigned long long s[BCAP];
    int T = g_thresh;
    int t = threadIdx.x;                           // 128 threads
    for (int b = T + blockIdx.x; b < HB; b += gridDim.x) {
        unsigned base = g_base[b];
        if (base >= (unsigned)NPRE) continue;      // ranks never read
        unsigned cnt = g_cnt[b];
        if (cnt == 0) continue;
        int m = (cnt < (unsigned)BCAP) ? (int)cnt : BCAP;
        if (m > 1) {
            int kmax = 2; while (kmax < m) kmax <<= 1;
            for (int i = t; i < kmax; i += 128) s[i] = (i < m) ? g_cand[base + i] : 0ull;
            __syncthreads();
            for (int k = 2; k <= kmax; k <<= 1) {
                for (int j = k >> 1; j > 0; j >>= 1) {
                    for (int p = t; p < (kmax >> 1); p += 128) {
                        int i = ((p & ~(j - 1)) << 1) | (p & (j - 1));
                        int x = i | j;
                        unsigned long long a = s[i], bb = s[x];
                        bool desc = ((i & k) == 0);
                        if (desc ? (a < bb) : (a > bb)) { s[i] = bb; s[x] = a; }
                    }
                    __syncthreads();
                }
            }
        }
        // decode ranks [base, base+cnt) ∩ [0, NPRE) straight from shared
        int lim = (int)cnt;
        if (base + lim > (unsigned)NPRE) lim = NPRE - (int)base;
        if (base + lim > (unsigned)CAND_MAX) lim = CAND_MAX - (int)base;
        for (int i = t; i < lim; i += 128) {
            unsigned long long key = (m > 1 && i < m) ? s[i] : g_cand[base + i];
            int r = (int)base + i;
            float y1 = 0.f, x1 = 0.f, y2 = 0.f, x2 = 0.f, sc = 0.f;
            unsigned idx = 0xFFFFFFFFu - (unsigned)(key & 0xFFFFFFFFull);
            if (idx < (unsigned)n) {
                sc = __uint_as_float((unsigned)(key >> 32));
                float4 a = ((const float4*)anch)[idx];   // [y1, x1, y2, x2]
                float4 e = ((const float4*)enc)[idx];    // [ty, tx, th, tw]
                float ha = a.z - a.x, wa = a.w - a.y;
                float cya = a.x + 0.5f * ha, cxa = a.y + 0.5f * wa;
                float cy = e.x * ha + cya;
                float cx = e.y * wa + cxa;
                float h  = expf(e.z) * ha;
                float w  = expf(e.w) * wa;
                y1 = cy - 0.5f * h; x1 = cx - 0.5f * w;
                y2 = cy + 0.5f * h; x2 = cx + 0.5f * w;
            }
            g_y1[r] = y1; g_x1[r] = x1; g_y2[r] = y2; g_x2[r] = x2;
            g_pa[r] = 0.7f * (y2 - y1) * (x2 - x1);
            g_scores[r] = sc;
        }
        __syncthreads();
    }
}

// ---------------- K5: IoU bitmask, transposed coalesced writes --------------
// iou > 0.7  <=>  1.7*inter > 0.7*areaA + 0.7*areaB
__global__ void mask_k(int col0) {
    if (*(volatile int*)&g_done) return;
    int bx = col0 + blockIdx.x;
    int by = blockIdx.y;
    if (bx >= NB || by > bx) return;

    __shared__ float4 colb[64];
    __shared__ float  colp[64];
    int t = threadIdx.x;
    int j = bx * 64 + t;
    colb[t] = make_float4(g_y1[j], g_x1[j], g_y2[j], g_x2[j]);
    colp[t] = g_pa[j];
    __syncthreads();

    int i = by * 64 + t;
    float y1 = g_y1[i], x1 = g_x1[i], y2 = g_y2[i], x2 = g_x2[i];
    float pa = g_pa[i];
    unsigned long long m = 0ull;

    if (bx > by) {
#pragma unroll 16
        for (int c = 0; c < 64; c++) {
            float4 cb = colb[c];
            float iy1 = fmaxf(y1, cb.x), ix1 = fmaxf(x1, cb.y);
            float iy2 = fminf(y2, cb.z), ix2 = fminf(x2, cb.w);
            float dy = fmaxf(iy2 - iy1, 0.f), dx = fmaxf(ix2 - ix1, 0.f);
            bool cond = fmaf(1.7f, dy * dx, -pa) > colp[c];
            m |= ((unsigned long long)cond) << c;
        }
    } else {  // diagonal block: only c > t
        for (int c = t + 1; c < 64; c++) {
            float4 cb = colb[c];
            float iy1 = fmaxf(y1, cb.x), ix1 = fmaxf(x1, cb.y);
            float iy2 = fminf(y2, cb.z), ix2 = fminf(x2, cb.w);
            float dy = fmaxf(iy2 - iy1, 0.f), dx = fmaxf(ix2 - ix1, 0.f);
            bool cond = fmaf(1.7f, dy * dx, -pa) > colp[c];
            m |= ((unsigned long long)cond) << c;
        }
    }
    g_maskT[bx][i] = m;   // coalesced across t
}

// ---------------- K6: NMS reduce — branchless high-MLP cross-OR -------------
__global__ void nms_part_k(int g0, int g1) {
    if (*(volatile int*)&g_done) return;
    __shared__ int                s_kept[NPOST];
    __shared__ unsigned long long s_alive[NB];
    __shared__ unsigned long long s_col[64];
    __shared__ unsigned long long s_cross, s_colOR, s_alivew;
    __shared__ int s_kc;
    int t = threadIdx.x;                       // 256 threads
    int kcount = g_kcount;
    for (int i = t; i < kcount; i += 256) s_kept[i] = g_kept[i];
    for (int i = t; i < NB; i += 256) s_alive[i] = g_alive[i];
    if (t == 0) { s_cross = 0ull; s_colOR = 0ull; }
    __syncthreads();

    if (g1 > NB) g1 = NB;
    for (int g = g0; g < g1; ++g) {
        int base = g * 64;
        int n = NPRE - base; if (n > 64) n = 64;
        // ---- Phase A: column words + branchless alive-masked cross-OR ------
        if (t < 64) {
            unsigned long long w = g_maskT[g][base + t];
            s_col[t] = w;
            if (w) atomicOr(&s_colOR, w);
        }
        {
            const unsigned long long* colgp = g_maskT[g];
            unsigned long long p = 0ull;
            int r = t;
            for (; r + 768 < base; r += 1024) {   // 4-wide for MLP
                unsigned long long a0 = colgp[r]       & (0ull - ((s_alive[(r)       >> 6] >> ((r)       & 63)) & 1ull));
                unsigned long long a1 = colgp[r + 256] & (0ull - ((s_alive[(r + 256) >> 6] >> ((r + 256) & 63)) & 1ull));
                unsigned long long a2 = colgp[r + 512] & (0ull - ((s_alive[(r + 512) >> 6] >> ((r + 512) & 63)) & 1ull));
                unsigned long long a3 = colgp[r + 768] & (0ull - ((s_alive[(r + 768) >> 6] >> ((r + 768) & 63)) & 1ull));
                p |= (a0 | a1) | (a2 | a3);
            }
            for (; r < base; r += 256)
                p |= colgp[r] & (0ull - ((s_alive[r >> 6] >> (r & 63)) & 1ull));
            if (p) atomicOr(&s_cross, p);
        }
        __syncthreads();
        // ---- Phase B: decision ---------------------------------------------
        unsigned long long cross = s_cross;
        unsigned long long colOR = s_colOR;
        unsigned long long rowmask = (n == 64) ? ~0ull : ((1ull << n) - 1ull);
        bool fast = (cross == 0ull && colOR == 0ull && kcount + n <= NPOST);
        if (fast) {
            if (t < n) s_kept[kcount + t] = base + t;
            if (t == 0) { s_kc = kcount + n; s_alivew = rowmask; }
        } else if (t == 0) {
            unsigned long long avail = (~cross) & rowmask;
            unsigned long long alivew = 0ull;
            int kc = kcount;
            while (avail && kc < NPOST) {
                int k1 = __ffsll((long long)avail) - 1;
                unsigned long long r = avail & (avail - 1);
                unsigned long long c1 = s_col[k1];
                int k2 = -1, k3 = -1, k4 = -1;
                unsigned long long c2 = 0, c3 = 0, c4 = 0;
                if (r) { k2 = __ffsll((long long)r) - 1; c2 = s_col[k2]; r &= r - 1;
                    if (r) { k3 = __ffsll((long long)r) - 1; c3 = s_col[k3]; r &= r - 1;
                        if (r) { k4 = __ffsll((long long)r) - 1; c4 = s_col[k4]; r &= r - 1; } } }
                unsigned long long m = c1;
                s_kept[kc++] = base + k1; alivew |= 1ull << k1;
                if (k2 >= 0 && kc < NPOST && !((m >> k2) & 1ull)) { s_kept[kc++] = base + k2; alivew |= 1ull << k2; m |= c2; }
                if (k3 >= 0 && kc < NPOST && !((m >> k3) & 1ull)) { s_kept[kc++] = base + k3; alivew |= 1ull << k3; m |= c3; }
                if (k4 >= 0 && kc < NPOST && !((m >> k4) & 1ull)) { s_kept[kc++] = base + k4; alivew |= 1ull << k4; m |= c4; }
                avail = r & ~m;
            }
            s_kc = kc; s_alivew = alivew;
        }
        __syncthreads();
        // ---- Phase C: bookkeeping ------------------------------------------
        kcount = s_kc;
        if (t == 0) { s_alive[g] = s_alivew; s_cross = 0ull; s_colOR = 0ull; }
        __syncthreads();
        if (kcount >= NPOST) break;
    }
    // epilogue
    int kc0 = g_kcount;
    for (int i = kc0 + t; i < kcount; i += 256) g_kept[i] = s_kept[i];
    for (int i = t; i < NB; i += 256) g_alive[i] = s_alive[i];
    if (t == 0) {
        g_kcount = kcount;
        if (kcount >= NPOST || g1 >= NB) g_done = 1;
    }
}

// ---------------- K7: write output + reset state for next replay ------------
__global__ void finish_k(float* __restrict__ out) {
    int gid = blockIdx.x * blockDim.x + threadIdx.x;
    int gs  = gridDim.x * blockDim.x;
    int kcount = g_kcount;
    for (int o = gid; o < NPOST; o += gs) {
        if (o < kcount) {
            int i = g_kept[o];
            ((float4*)out)[o] = make_float4(g_y1[i], g_x1[i], g_y2[i], g_x2[i]);
            out[NPOST * 4 + o] = g_scores[i];
        } else {
            ((float4*)out)[o] = make_float4(0.f, 0.f, 0.f, 0.f);
            out[NPOST * 4 + o] = 0.f;
        }
    }
    // reset for next replay (graph edge serializes this after the reads above)
    for (int i = gid; i < HB; i += gs) { g_hist[i] = 0u; g_cnt[i] = 0u; }
    for (int i = gid; i < NB; i += gs) g_alive[i] = 0ull;
    if (gid == 0) { g_kcount = 0; g_done = 0; g_nstash = 0; }
}

// ---------------- launch ----------------------------------------------------
extern "C" void kernel_launch(void* const* d_in, const int* in_sizes, int n_in,
                              void* d_out, int out_size) {
    const float* enc    = (const float*)d_in[0];  // encoded_bboxes [N,4]
    const float* anch   = (const float*)d_in[1];  // anchors        [N,4]
    const float* scores = (const float*)d_in[2];  // scores         [N]
    float* out = (float*)d_out;                   // 2000*4 boxes + 2000 scores
    int n = in_sizes[2];
    int n4 = n / 4;

    scan_stash_k<<<1024, 256>>>((const float4*)scores, n4);
    thresh_k<<<1, 1024>>>((const float4*)scores, n4);
    compact_k<<<512, 256>>>((const float4*)scores, n4);
    bsort_decode_k<<<148, 128>>>(enc, anch, n);

    // two-chunk mask+NMS with early-exit flag; expected exit <= group 40
    mask_k<<<dim3(40, 40), 64>>>(0);
    nms_part_k<<<1, 256>>>(0, 40);
    mask_k<<<dim3(54, 94), 64>>>(40);
    nms_part_k<<<1, 256>>>(40, 94);

    finish_k<<<128, 256>>>(out);
}

// round 11
// speedup vs baseline: 1.4369x; 1.0119x over previous
#include <cuda_runtime.h>
#include <stdint.h>

// Problem constants (fixed by the reference).
#define NPRE     6000
#define NPOST    2000
#define NB       94          // ceil(NPRE/64)
#define NROWS    (NB * 64)   // 6016, padded
#define HB       32768       // score histogram buckets (scores in [0,1))
#define BCAP     256         // per-bucket sort capacity
#define SCUT     (HB - 256)  // stash cut bucket
#define STASH_CAP 32768
#define SLOCAL   256         // per-block stash buffer

// ---------------- persistent device scratch (static zero-init at load) ------
__device__ unsigned           g_hist[HB];   // fallback path only
__device__ unsigned           g_base[HB];   // fallback path only
__device__ int                g_thresh;     // fallback path only
__device__ int                g_nstash;
__device__ unsigned long long g_stash[STASH_CAP];
// SoA boxes (padded rows >= NPRE are never written -> stay zero)
__device__ float              g_y1[NROWS], g_x1[NROWS], g_y2[NROWS], g_x2[NROWS];
__device__ float              g_pa[NROWS];      // 0.7f * area
__device__ float              g_scores[NROWS];
// transposed mask: g_maskT[col_group][row]
__device__ unsigned long long g_maskT[NB][NROWS];
__device__ unsigned long long g_alive[NB];
__device__ int                g_kept[NPOST];
__device__ int                g_kcount;
__device__ int                g_done;

__device__ __forceinline__ int score_bucket(float s) {
    int b = (int)(s * 32768.0f);
    return max(0, min(HB - 1, b));
}

// ---------------- K1: pure scan + block-aggregated stash --------------------
__global__ void scan_stash_k(const float4* __restrict__ s4, int n4) {
    __shared__ unsigned long long s_stash[SLOCAL];
    __shared__ int s_scnt, s_sbase;
    if (threadIdx.x == 0) s_scnt = 0;
    __syncthreads();
    int i = blockIdx.x * blockDim.x + threadIdx.x;
    int stride = gridDim.x * blockDim.x;
    for (; i < n4; i += stride) {
        float4 v = s4[i];
        float e[4] = {v.x, v.y, v.z, v.w};
#pragma unroll
        for (int c = 0; c < 4; c++) {
            if (score_bucket(e[c]) >= SCUT) {
                unsigned idx = (unsigned)(4 * i + c);
                unsigned long long key =
                    ((unsigned long long)__float_as_uint(e[c]) << 32)
                  | (unsigned long long)(0xFFFFFFFFu - idx);
                int p = atomicAdd(&s_scnt, 1);
                if (p < SLOCAL) s_stash[p] = key;
                else {                        // rare overflow: direct global
                    int q = atomicAdd(&g_nstash, 1);
                    if (q < STASH_CAP) g_stash[q] = key;
                }
            }
        }
    }
    __syncthreads();
    int cnt = s_scnt; if (cnt > SLOCAL) cnt = SLOCAL;
    if (threadIdx.x == 0) s_sbase = (cnt > 0) ? atomicAdd(&g_nstash, cnt) : 0;
    __syncthreads();
    for (int k = threadIdx.x; k < cnt; k += blockDim.x) {
        int q = s_sbase + k;
        if (q < STASH_CAP) g_stash[q] = s_stash[k];
    }
}

// ---------------- K2: fallback-only threshold (no-op on fast path) ----------
__global__ void thresh_k(const float4* __restrict__ s4, int n4) {
    int ns = g_nstash;
    if (ns >= NPRE && ns <= STASH_CAP) return;   // fast path: nothing to do
    __shared__ unsigned sbig[1024];
    int t = threadIdx.x;                         // 1024 threads
    for (int i = t; i < n4; i += 1024) {
        float4 v = s4[i];
        atomicAdd(&g_hist[score_bucket(v.x)], 1u);
        atomicAdd(&g_hist[score_bucket(v.y)], 1u);
        atomicAdd(&g_hist[score_bucket(v.z)], 1u);
        atomicAdd(&g_hist[score_bucket(v.w)], 1u);
    }
    __syncthreads();
    int lo = HB - (t + 1) * 32;
    unsigned cnts[32];
    unsigned sum = 0;
#pragma unroll
    for (int b = 0; b < 32; b++) { cnts[b] = g_hist[lo + b]; sum += cnts[b]; }
    sbig[t] = sum;
    __syncthreads();
    for (int off = 1; off < 1024; off <<= 1) {
        unsigned v = (t >= off) ? sbig[t - off] : 0u;
        __syncthreads();
        sbig[t] += v;
        __syncthreads();
    }
    unsigned run = sbig[t] - sum;
    for (int b = 31; b >= 0; --b) {
        g_base[lo + b] = run;
        unsigned c = cnts[b];
        if (run < (unsigned)NPRE && run + c >= (unsigned)NPRE) g_thresh = lo + b;
        run += c;
    }
    if (t == 1023 && sbig[1023] < (unsigned)NPRE) g_thresh = 0;
}

// ---------------- K3: per-bucket gather + sort + decode (fused) -------------
// Fast path: 256 blocks, block b' owns bucket HB-1-b'. Each block scans the
// L2-resident stash, counts keys above its bucket (exact rank base), collects
// its own keys, sorts them, and decodes straight into the SoA box arrays.
__global__ void sortdecode_k(const float* __restrict__ enc,
                             const float* __restrict__ anch,
                             const float* __restrict__ scores, int n) {
    __shared__ unsigned long long s[BCAP];
    __shared__ int s_cnt, s_above;
    int t = threadIdx.x;                         // 256 threads
    int ns = g_nstash;
    bool ok = (ns >= NPRE && ns <= STASH_CAP);

    if (ok) {
        int b = HB - 1 - blockIdx.x;             // gridDim.x == 256
        if (t == 0) { s_cnt = 0; s_above = 0; }
        __syncthreads();
        int above = 0;
        for (int i = t; i < ns; i += 256) {
            unsigned long long key = g_stash[i];
            int kb = score_bucket(__uint_as_float((unsigned)(key >> 32)));
            if (kb > b) above++;
            else if (kb == b) {
                int p = atomicAdd(&s_cnt, 1);
                if (p < BCAP) s[p] = key;
            }
        }
        if (above) atomicAdd(&s_above, above);
        __syncthreads();
        int base = s_above;
        int cnt = s_cnt; if (cnt > BCAP) cnt = BCAP;
        if (base >= NPRE || cnt == 0) return;
        // bitonic sort descending over pow2 region
        int kmax = 1; while (kmax < cnt) kmax <<= 1;
        for (int i = t; i < kmax; i += 256) if (i >= cnt) s[i] = 0ull;
        __syncthreads();
        for (int k = 2; k <= kmax; k <<= 1) {
            for (int j = k >> 1; j > 0; j >>= 1) {
                for (int p = t; p < (kmax >> 1); p += 256) {
                    int i = ((p & ~(j - 1)) << 1) | (p & (j - 1));
                    int x = i | j;
                    unsigned long long a = s[i], bb = s[x];
                    bool desc = ((i & k) == 0);
                    if (desc ? (a < bb) : (a > bb)) { s[i] = bb; s[x] = a; }
                }
                __syncthreads();
            }
        }
        int lim = cnt;
        if (base + lim > NPRE) lim = NPRE - base;
        for (int i = t; i < lim; i += 256) {
            unsigned long long key = s[i];
            int r = base + i;
            float y1 = 0.f, x1 = 0.f, y2 = 0.f, x2 = 0.f, sc = 0.f;
            unsigned idx = 0xFFFFFFFFu - (unsigned)(key & 0xFFFFFFFFull);
            if (idx < (unsigned)n) {
                sc = __uint_as_float((unsigned)(key >> 32));
                float4 a = ((const float4*)anch)[idx];   // [y1, x1, y2, x2]
                float4 e = ((const float4*)enc)[idx];    // [ty, tx, th, tw]
                float ha = a.z - a.x, wa = a.w - a.y;
                float cya = a.x + 0.5f * ha, cxa = a.y + 0.5f * wa;
                float cy = e.x * ha + cya;
                float cx = e.y * wa + cxa;
                float h  = expf(e.z) * ha;
                float w  = expf(e.w) * wa;
                y1 = cy - 0.5f * h; x1 = cx - 0.5f * w;
                y2 = cy + 0.5f * h; x2 = cx + 0.5f * w;
            }
            g_y1[r] = y1; g_x1[r] = x1; g_y2[r] = y2; g_x2[r] = x2;
            g_pa[r] = 0.7f * (y2 - y1) * (x2 - x1);
            g_scores[r] = sc;
        }
        return;
    }

    // ---- exact fallback (never taken for this data): gather from full scan --
    int T = g_thresh;
    for (int b = T + blockIdx.x; b < HB; b += gridDim.x) {
        unsigned base = g_base[b];
        if (base >= (unsigned)NPRE) continue;
        if (t == 0) s_cnt = 0;
        __syncthreads();
        for (int i = t; i < n; i += 256) {
            float sv = scores[i];
            if (score_bucket(sv) == b) {
                int p = atomicAdd(&s_cnt, 1);
                if (p < BCAP)
                    s[p] = ((unsigned long long)__float_as_uint(sv) << 32)
                         | (unsigned long long)(0xFFFFFFFFu - (unsigned)i);
            }
        }
        __syncthreads();
        int cnt = s_cnt; if (cnt > BCAP) cnt = BCAP;
        if (cnt == 0) { __syncthreads(); continue; }
        int kmax = 1; while (kmax < cnt) kmax <<= 1;
        for (int i = t; i < kmax; i += 256) if (i >= cnt) s[i] = 0ull;
        __syncthreads();
        for (int k = 2; k <= kmax; k <<= 1) {
            for (int j = k >> 1; j > 0; j >>= 1) {
                for (int p = t; p < (kmax >> 1); p += 256) {
                    int i = ((p & ~(j - 1)) << 1) | (p & (j - 1));
                    int x = i | j;
                    unsigned long long a = s[i], bb = s[x];
                    bool desc = ((i & k) == 0);
                    if (desc ? (a < bb) : (a > bb)) { s[i] = bb; s[x] = a; }
                }
                __syncthreads();
            }
        }
        int lim = cnt;
        if ((int)base + lim > NPRE) lim = NPRE - (int)base;
        for (int i = t; i < lim; i += 256) {
            unsigned long long key = s[i];
            int r = (int)base + i;
            float y1 = 0.f, x1 = 0.f, y2 = 0.f, x2 = 0.f, sc = 0.f;
            unsigned idx = 0xFFFFFFFFu - (unsigned)(key & 0xFFFFFFFFull);
            if (idx < (unsigned)n) {
                sc = __uint_as_float((unsigned)(key >> 32));
                float4 a = ((const float4*)anch)[idx];
                float4 e = ((const float4*)enc)[idx];
                float ha = a.z - a.x, wa = a.w - a.y;
                float cya = a.x + 0.5f * ha, cxa = a.y + 0.5f * wa;
                float cy = e.x * ha + cya;
                float cx = e.y * wa + cxa;
                float h  = expf(e.z) * ha;
                float w  = expf(e.w) * wa;
                y1 = cy - 0.5f * h; x1 = cx - 0.5f * w;
                y2 = cy + 0.5f * h; x2 = cx + 0.5f * w;
            }
            g_y1[r] = y1; g_x1[r] = x1; g_y2[r] = y2; g_x2[r] = x2;
            g_pa[r] = 0.7f * (y2 - y1) * (x2 - x1);
            g_scores[r] = sc;
        }
        __syncthreads();
    }
}

// ---------------- K4: IoU bitmask, transposed coalesced writes --------------
// iou > 0.7  <=>  1.7*inter > 0.7*areaA + 0.7*areaB
__global__ void mask_k(int col0) {
    if (*(volatile int*)&g_done) return;
    int bx = col0 + blockIdx.x;
    int by = blockIdx.y;
    if (bx >= NB || by > bx) return;

    __shared__ float4 colb[64];
    __shared__ float  colp[64];
    int t = threadIdx.x;
    int j = bx * 64 + t;
    colb[t] = make_float4(g_y1[j], g_x1[j], g_y2[j], g_x2[j]);
    colp[t] = g_pa[j];
    __syncthreads();

    int i = by * 64 + t;
    float y1 = g_y1[i], x1 = g_x1[i], y2 = g_y2[i], x2 = g_x2[i];
    float pa = g_pa[i];
    unsigned long long m = 0ull;

    if (bx > by) {
#pragma unroll 16
        for (int c = 0; c < 64; c++) {
            float4 cb = colb[c];
            float iy1 = fmaxf(y1, cb.x), ix1 = fmaxf(x1, cb.y);
            float iy2 = fminf(y2, cb.z), ix2 = fminf(x2, cb.w);
            float dy = fmaxf(iy2 - iy1, 0.f), dx = fmaxf(ix2 - ix1, 0.f);
            bool cond = fmaf(1.7f, dy * dx, -pa) > colp[c];
            m |= ((unsigned long long)cond) << c;
        }
    } else {  // diagonal block: only c > t
        for (int c = t + 1; c < 64; c++) {
            float4 cb = colb[c];
            float iy1 = fmaxf(y1, cb.x), ix1 = fmaxf(x1, cb.y);
            float iy2 = fminf(y2, cb.z), ix2 = fminf(x2, cb.w);
            float dy = fmaxf(iy2 - iy1, 0.f), dx = fmaxf(ix2 - ix1, 0.f);
            bool cond = fmaf(1.7f, dy * dx, -pa) > colp[c];
            m |= ((unsigned long long)cond) << c;
        }
    }
    g_maskT[bx][i] = m;   // coalesced across t
}

// ---------------- K5: NMS reduce — parallel emit when no in-group pairs -----
__global__ void nms_part_k(int g0, int g1) {
    if (*(volatile int*)&g_done) return;
    __shared__ int                s_kept[NPOST];
    __shared__ unsigned long long s_alive[NB];
    __shared__ unsigned long long s_col[64];
    __shared__ unsigned long long s_cross, s_colOR, s_alivew;
    __shared__ int s_kc;
    int t = threadIdx.x;                       // 256 threads
    int kcount = g_kcount;
    for (int i = t; i < kcount; i += 256) s_kept[i] = g_kept[i];
    for (int i = t; i < NB; i += 256) s_alive[i] = g_alive[i];
    if (t == 0) { s_cross = 0ull; s_colOR = 0ull; s_alivew = 0ull; }
    __syncthreads();

    if (g1 > NB) g1 = NB;
    for (int g = g0; g < g1; ++g) {
        int base = g * 64;
        int n = NPRE - base; if (n > 64) n = 64;
        // ---- Phase A: column words + branchless alive-masked cross-OR ------
        if (t < 64) {
            unsigned long long w = g_maskT[g][base + t];
            s_col[t] = w;
            if (w) atomicOr(&s_colOR, w);
        }
        {
            const unsigned long long* colgp = g_maskT[g];
            unsigned long long p = 0ull;
            int r = t;
            for (; r + 768 < base; r += 1024) {   // 4-wide for MLP
                unsigned long long a0 = colgp[r]       & (0ull - ((s_alive[(r)       >> 6] >> ((r)       & 63)) & 1ull));
                unsigned long long a1 = colgp[r + 256] & (0ull - ((s_alive[(r + 256) >> 6] >> ((r + 256) & 63)) & 1ull));
                unsigned long long a2 = colgp[r + 512] & (0ull - ((s_alive[(r + 512) >> 6] >> ((r + 512) & 63)) & 1ull));
                unsigned long long a3 = colgp[r + 768] & (0ull - ((s_alive[(r + 768) >> 6] >> ((r + 768) & 63)) & 1ull));
                p |= (a0 | a1) | (a2 | a3);
            }
            for (; r < base; r += 256)
                p |= colgp[r] & (0ull - ((s_alive[r >> 6] >> (r & 63)) & 1ull));
            if (p) atomicOr(&s_cross, p);
        }
        __syncthreads();
        // ---- Phase B: decision ---------------------------------------------
        unsigned long long cross = s_cross;
        unsigned long long colOR = s_colOR;
        unsigned long long rowmask = (n == 64) ? ~0ull : ((1ull << n) - 1ull);
        if (colOR == 0ull) {
            // no in-group suppression possible: greedy == drop cross-suppressed
            unsigned long long keep = (~cross) & rowmask;
            int budget = NPOST - kcount;
            if (t < 64 && ((keep >> t) & 1ull)) {
                int rank = __popcll(keep & ((1ull << t) - 1ull));
                if (rank < budget) {
                    s_kept[kcount + rank] = base + t;
                    atomicOr(&s_alivew, 1ull << t);
                }
            }
            if (t == 0) {
                int pc = __popcll(keep);
                s_kc = kcount + (pc < budget ? pc : budget);
            }
        } else if (t == 0) {
            unsigned long long avail = (~cross) & rowmask;
            unsigned long long alivew = 0ull;
            int kc = kcount;
            while (avail && kc < NPOST) {
                int k1 = __ffsll((long long)avail) - 1;
                unsigned long long r = avail & (avail - 1);
                unsigned long long c1 = s_col[k1];
                int k2 = -1, k3 = -1, k4 = -1;
                unsigned long long c2 = 0, c3 = 0, c4 = 0;
                if (r) { k2 = __ffsll((long long)r) - 1; c2 = s_col[k2]; r &= r - 1;
                    if (r) { k3 = __ffsll((long long)r) - 1; c3 = s_col[k3]; r &= r - 1;
                        if (r) { k4 = __ffsll((long long)r) - 1; c4 = s_col[k4]; r &= r - 1; } } }
                unsigned long long m = c1;
                s_kept[kc++] = base + k1; alivew |= 1ull << k1;
                if (k2 >= 0 && kc < NPOST && !((m >> k2) & 1ull)) { s_kept[kc++] = base + k2; alivew |= 1ull << k2; m |= c2; }
                if (k3 >= 0 && kc < NPOST && !((m >> k3) & 1ull)) { s_kept[kc++] = base + k3; alivew |= 1ull << k3; m |= c3; }
                if (k4 >= 0 && kc < NPOST && !((m >> k4) & 1ull)) { s_kept[kc++] = base + k4; alivew |= 1ull << k4; m |= c4; }
                avail = r & ~m;
            }
            s_kc = kc; s_alivew = alivew;
        }
        __syncthreads();
        // ---- Phase C: bookkeeping ------------------------------------------
        kcount = s_kc;
        if (t == 0) { s_alive[g] = s_alivew; s_cross = 0ull; s_colOR = 0ull; s_alivew = 0ull; }
        __syncthreads();
        if (kcount >= NPOST) break;
    }
    // epilogue
    int kc0 = g_kcount;
    for (int i = kc0 + t; i < kcount; i += 256) g_kept[i] = s_kept[i];
    for (int i = t; i < NB; i += 256) g_alive[i] = s_alive[i];
    if (t == 0) {
        g_kcount = kcount;
        if (kcount >= NPOST || g1 >= NB) g_done = 1;
    }
}

// ---------------- K6: write output + reset state for next replay ------------
__global__ void finish_k(float* __restrict__ out) {
    int gid = blockIdx.x * blockDim.x + threadIdx.x;
    int gs  = gridDim.x * blockDim.x;
    int kcount = g_kcount;
    for (int o = gid; o < NPOST; o += gs) {
        if (o < kcount) {
            int i = g_kept[o];
            ((float4*)out)[o] = make_float4(g_y1[i], g_x1[i], g_y2[i], g_x2[i]);
            out[NPOST * 4 + o] = g_scores[i];
        } else {
            ((float4*)out)[o] = make_float4(0.f, 0.f, 0.f, 0.f);
            out[NPOST * 4 + o] = 0.f;
        }
    }
    // reset for next replay (graph edge serializes this after the reads above)
    for (int i = gid; i < HB; i += gs) g_hist[i] = 0u;
    for (int i = gid; i < NB; i += gs) g_alive[i] = 0ull;
    if (gid == 0) { g_kcount = 0; g_done = 0; g_nstash = 0; }
}

// ---------------- launch ----------------------------------------------------
extern "C" void kernel_launch(void* const* d_in, const int* in_sizes, int n_in,
                              void* d_out, int out_size) {
    const float* enc    = (const float*)d_in[0];  // encoded_bboxes [N,4]
    const float* anch   = (const float*)d_in[1];  // anchors        [N,4]
    const float* scores = (const float*)d_in[2];  // scores         [N]
    float* out = (float*)d_out;                   // 2000*4 boxes + 2000 scores
    int n = in_sizes[2];
    int n4 = n / 4;

    scan_stash_k<<<1024, 256>>>((const float4*)scores, n4);
    thresh_k<<<1, 1024>>>((const float4*)scores, n4);
    sortdecode_k<<<256, 256>>>(enc, anch, scores, n);

    // two-chunk mask+NMS with early-exit flag; expected exit <= group 40
    mask_k<<<dim3(40, 40), 64>>>(0);
    nms_part_k<<<1, 256>>>(0, 40);
    mask_k<<<dim3(54, 94), 64>>>(40);
    nms_part_k<<<1, 256>>>(40, 94);

    finish_k<<<128, 256>>>(out);
}